// round 1
// baseline (speedup 1.0000x reference)
#include <cuda_runtime.h>

// =====================================================================
// Photonic circuit simulator, Fock cutoff 2, 6 wires -> 64 complex amps.
// Wire w <-> bit (5 - w) of the flat state index (wire 0 most significant).
//
// Key analytic reduction: the encoding acts on |0...0>, so the first
// squeeze / beamsplitter / rotation layers are identity-up-to-scalar and
// the state after the full encoding is a PRODUCT state:
//   amp(n) = prod_w f_w(n_w)
//   f_w(0) = sqrt(sech x[2w]) * exp(-x[28+2w]^2/2) * sqrt(sech x[46+2w])
//   f_w(1) = f-base * x[28+2w] * sech(x[46+2w])^1.5/sqrt(sech..) ... i.e.
//            d01 * pref * d12 * r * e^{i(x[29+2w] + x[40+w] + x[58+w])}
// (x[12:28] never influence the circuit; x is still used in the residual.)
// Then 2 variational layers of gates are applied with compile-time index
// patterns so the whole 64-complex state stays in registers.
// =====================================================================

// ---- single-wire gates, mask M = bit of the wire ----

template<int M>
__device__ __forceinline__ void applyRot(float* sr, float* si, float cr, float ci) {
#pragma unroll
    for (int p = 0; p < 32; ++p) {
        const int j = ((((p & ~(M - 1)) << 1) | (p & (M - 1))) | M);
        float a = sr[j], b = si[j];
        sr[j] = a * cr - b * ci;
        si[j] = a * ci + b * cr;
    }
}

template<int M>
__device__ __forceinline__ void applySq(float* sr, float* si, float d0, float d1) {
#pragma unroll
    for (int p = 0; p < 32; ++p) {
        const int j0 = (((p & ~(M - 1)) << 1) | (p & (M - 1)));
        const int j1 = j0 | M;
        sr[j0] *= d0; si[j0] *= d0;
        sr[j1] *= d1; si[j1] *= d1;
    }
}

// Real 2x2 displacement (var layers have phi = 0):
// new0 = m00*s0 + m01*s1 ; new1 = m10*s0 + m11*s1   (all m real)
template<int M>
__device__ __forceinline__ void applyDispReal(float* sr, float* si,
                                              float m00, float m01, float m10, float m11) {
#pragma unroll
    for (int p = 0; p < 32; ++p) {
        const int j0 = (((p & ~(M - 1)) << 1) | (p & (M - 1)));
        const int j1 = j0 | M;
        float a0 = sr[j0], b0 = si[j0], a1 = sr[j1], b1 = si[j1];
        sr[j0] = m00 * a0 + m01 * a1;
        si[j0] = m00 * b0 + m01 * b1;
        sr[j1] = m10 * a0 + m11 * a1;
        si[j1] = m10 * b0 + m11 * b1;
    }
}

// ---- beamsplitter on wires (i, i+1): HI = 2*LO, LO = 1 << (4-i) ----
// new01 = c*s01 + es*s10 ; new10 = -conj(es)*s01 + c*s10 ; s11 *= cos(2 theta)
template<int LO>
__device__ __forceinline__ void applyBS(float* sr, float* si,
                                        float c, float esr, float esi, float c2) {
    const int HI = LO << 1;
#pragma unroll
    for (int p = 0; p < 16; ++p) {
        const int j00 = (((p & ~(LO - 1)) << 2) | (p & (LO - 1)));
        const int j01 = j00 | LO;
        const int j10 = j00 | HI;
        const int j11 = j00 | HI | LO;
        float a01 = sr[j01], b01 = si[j01];
        float a10 = sr[j10], b10 = si[j10];
        sr[j01] = c * a01 + esr * a10 - esi * b10;
        si[j01] = c * b01 + esr * b10 + esi * a10;
        sr[j10] = c * a10 - esr * a01 - esi * b01;
        si[j10] = c * b10 - esr * b01 + esi * a01;
        sr[j11] *= c2;
        si[j11] *= c2;
    }
}

// ---- product-state expansion: add wire W (mask 1<<(5-W)) ----
template<int W>
__device__ __forceinline__ void expandWire(float* sr, float* si,
                                           float f0, float f1r, float f1i) {
    const int M = 1 << (5 - W);
#pragma unroll
    for (int t = 0; t < (1 << W); ++t) {
        const int j = t << (6 - W);
        float a = sr[j], b = si[j];
        sr[j | M] = a * f1r - b * f1i;
        si[j | M] = a * f1i + b * f1r;
        sr[j] = a * f0;
        si[j] = b * f0;
    }
}

__device__ __forceinline__ float fast_sech(float r) {
    float e = __expf(r);
    return __fdividef(2.0f, e + __fdividef(1.0f, e));
}

__device__ __forceinline__ void bs_coeffs(float th, float ph,
                                          float& c, float& esr, float& esi, float& c2) {
    float st, ct, sp, cp;
    __sincosf(th, &st, &ct);
    __sincosf(ph, &sp, &cp);
    c = ct; esr = st * cp; esi = st * sp;
    c2 = 1.0f - 2.0f * st * st;   // cos(2 theta)
}

// one variational layer, v = var + 50*l
__device__ __forceinline__ void apply_layer(float* sr, float* si, const float* __restrict__ v) {
    float c, esr, esi, c2;
    // BS set 1: v[0..9], wires (i,i+1) -> LO = 1<<(4-i)
    bs_coeffs(v[0], v[1], c, esr, esi, c2); applyBS<16>(sr, si, c, esr, esi, c2);
    bs_coeffs(v[2], v[3], c, esr, esi, c2); applyBS<8 >(sr, si, c, esr, esi, c2);
    bs_coeffs(v[4], v[5], c, esr, esi, c2); applyBS<4 >(sr, si, c, esr, esi, c2);
    bs_coeffs(v[6], v[7], c, esr, esi, c2); applyBS<2 >(sr, si, c, esr, esi, c2);
    bs_coeffs(v[8], v[9], c, esr, esi, c2); applyBS<1 >(sr, si, c, esr, esi, c2);
    // rotations: v[10+w], wire w -> mask 1<<(5-w)
    {
        float s_, c_;
        __sincosf(v[10], &s_, &c_); applyRot<32>(sr, si, c_, s_);
        __sincosf(v[11], &s_, &c_); applyRot<16>(sr, si, c_, s_);
        __sincosf(v[12], &s_, &c_); applyRot<8 >(sr, si, c_, s_);
        __sincosf(v[13], &s_, &c_); applyRot<4 >(sr, si, c_, s_);
        __sincosf(v[14], &s_, &c_); applyRot<2 >(sr, si, c_, s_);
        __sincosf(v[15], &s_, &c_); applyRot<1 >(sr, si, c_, s_);
    }
    // squeezers: v[16+w]
    {
        float sh, d0;
        sh = fast_sech(v[16]); d0 = sqrtf(sh); applySq<32>(sr, si, d0, sh * d0);
        sh = fast_sech(v[17]); d0 = sqrtf(sh); applySq<16>(sr, si, d0, sh * d0);
        sh = fast_sech(v[18]); d0 = sqrtf(sh); applySq<8 >(sr, si, d0, sh * d0);
        sh = fast_sech(v[19]); d0 = sqrtf(sh); applySq<4 >(sr, si, d0, sh * d0);
        sh = fast_sech(v[20]); d0 = sqrtf(sh); applySq<2 >(sr, si, d0, sh * d0);
        sh = fast_sech(v[21]); d0 = sqrtf(sh); applySq<1 >(sr, si, d0, sh * d0);
    }
    // BS set 2: v[22..31]
    bs_coeffs(v[22], v[23], c, esr, esi, c2); applyBS<16>(sr, si, c, esr, esi, c2);
    bs_coeffs(v[24], v[25], c, esr, esi, c2); applyBS<8 >(sr, si, c, esr, esi, c2);
    bs_coeffs(v[26], v[27], c, esr, esi, c2); applyBS<4 >(sr, si, c, esr, esi, c2);
    bs_coeffs(v[28], v[29], c, esr, esi, c2); applyBS<2 >(sr, si, c, esr, esi, c2);
    bs_coeffs(v[30], v[31], c, esr, esi, c2); applyBS<1 >(sr, si, c, esr, esi, c2);
    // rotations: v[32+w]
    {
        float s_, c_;
        __sincosf(v[32], &s_, &c_); applyRot<32>(sr, si, c_, s_);
        __sincosf(v[33], &s_, &c_); applyRot<16>(sr, si, c_, s_);
        __sincosf(v[34], &s_, &c_); applyRot<8 >(sr, si, c_, s_);
        __sincosf(v[35], &s_, &c_); applyRot<4 >(sr, si, c_, s_);
        __sincosf(v[36], &s_, &c_); applyRot<2 >(sr, si, c_, s_);
        __sincosf(v[37], &s_, &c_); applyRot<1 >(sr, si, c_, s_);
    }
    // displacements (phi = 0): v[38+w]
    {
        float r, pf;
        r = v[38]; pf = __expf(-0.5f * r * r); applyDispReal<32>(sr, si, pf, -pf * r, pf * r, pf * (1.0f - r * r));
        r = v[39]; pf = __expf(-0.5f * r * r); applyDispReal<16>(sr, si, pf, -pf * r, pf * r, pf * (1.0f - r * r));
        r = v[40]; pf = __expf(-0.5f * r * r); applyDispReal<8 >(sr, si, pf, -pf * r, pf * r, pf * (1.0f - r * r));
        r = v[41]; pf = __expf(-0.5f * r * r); applyDispReal<4 >(sr, si, pf, -pf * r, pf * r, pf * (1.0f - r * r));
        r = v[42]; pf = __expf(-0.5f * r * r); applyDispReal<2 >(sr, si, pf, -pf * r, pf * r, pf * (1.0f - r * r));
        r = v[43]; pf = __expf(-0.5f * r * r); applyDispReal<1 >(sr, si, pf, -pf * r, pf * r, pf * (1.0f - r * r));
    }
    // Kerr (= rotation at cutoff 2): v[44+w]
    {
        float s_, c_;
        __sincosf(v[44], &s_, &c_); applyRot<32>(sr, si, c_, s_);
        __sincosf(v[45], &s_, &c_); applyRot<16>(sr, si, c_, s_);
        __sincosf(v[46], &s_, &c_); applyRot<8 >(sr, si, c_, s_);
        __sincosf(v[47], &s_, &c_); applyRot<4 >(sr, si, c_, s_);
        __sincosf(v[48], &s_, &c_); applyRot<2 >(sr, si, c_, s_);
        __sincosf(v[49], &s_, &c_); applyRot<1 >(sr, si, c_, s_);
    }
}

// per-wire factors of the post-encoding product state
__device__ __forceinline__ void wire_factors(const float* __restrict__ xp, int w,
                                             float& f0, float& f1r, float& f1i) {
    float r1   = xp[2 * w];
    float dr   = xp[28 + 2 * w];
    float dphi = xp[29 + 2 * w];
    float kerr = xp[40 + w];
    float r2   = xp[46 + 2 * w];
    float rot2 = xp[58 + w];

    float sech1 = fast_sech(r1);
    float d01   = sqrtf(sech1);
    float pref  = __expf(-0.5f * dr * dr);
    float sech2 = fast_sech(r2);
    float d02   = sqrtf(sech2);
    float d12   = sech2 * d02;

    float base = d01 * pref;
    f0 = base * d02;
    float A = base * d12 * dr;
    float sA, cA;
    __sincosf(dphi + kerr + rot2, &sA, &cA);
    f1r = A * cA;
    f1i = A * sA;
}

extern "C" __global__ void __launch_bounds__(128)
ffblock_kernel(const float* __restrict__ x, const float* __restrict__ var,
               const float* __restrict__ gamma, const float* __restrict__ beta,
               float* __restrict__ out, int nsamp)
{
    int t = blockIdx.x * blockDim.x + threadIdx.x;
    if (t >= nsamp) return;
    const float* xp = x + (size_t)t * 64;

    float sr[64], si[64];
    sr[0] = 1.0f; si[0] = 0.0f;

    // build product state (encoding)
    {
        float f0, f1r, f1i;
        wire_factors(xp, 0, f0, f1r, f1i); expandWire<0>(sr, si, f0, f1r, f1i);
        wire_factors(xp, 1, f0, f1r, f1i); expandWire<1>(sr, si, f0, f1r, f1i);
        wire_factors(xp, 2, f0, f1r, f1i); expandWire<2>(sr, si, f0, f1r, f1i);
        wire_factors(xp, 3, f0, f1r, f1i); expandWire<3>(sr, si, f0, f1r, f1i);
        wire_factors(xp, 4, f0, f1r, f1i); expandWire<4>(sr, si, f0, f1r, f1i);
        wire_factors(xp, 5, f0, f1r, f1i); expandWire<5>(sr, si, f0, f1r, f1i);
    }

    // variational layers
    apply_layer(sr, si, var);
    apply_layer(sr, si, var + 50);

    // probs + residual, accumulate LayerNorm stats
    float sum = 0.0f, sumsq = 0.0f;
#pragma unroll
    for (int j = 0; j < 64; ++j) {
        float p = sr[j] * sr[j] + si[j] * si[j];
        float y = p + xp[j];
        sr[j] = y;                 // reuse state regs for y
        sum += y;
        sumsq += y * y;
    }
    float mean = sum * (1.0f / 64.0f);
    float varr = sumsq * (1.0f / 64.0f) - mean * mean;
    float inv = rsqrtf(varr + 1e-5f);

    float* op = out + (size_t)t * 64;
#pragma unroll
    for (int j = 0; j < 64; ++j) {
        op[j] = (sr[j] - mean) * inv * gamma[j] + beta[j];
    }
}

extern "C" void kernel_launch(void* const* d_in, const int* in_sizes, int n_in,
                              void* d_out, int out_size) {
    const float* x     = (const float*)d_in[0];
    const float* var   = (const float*)d_in[1];
    const float* gamma = (const float*)d_in[2];
    const float* beta  = (const float*)d_in[3];
    float* out = (float*)d_out;

    int nsamp = in_sizes[0] / 64;
    int threads = 128;
    int blocks = (nsamp + threads - 1) / threads;
    ffblock_kernel<<<blocks, threads>>>(x, var, gamma, beta, out, nsamp);
}

// round 2
// speedup vs baseline: 1.7510x; 1.7510x over previous
#include <cuda_runtime.h>

// =====================================================================
// Photonic circuit (6 wires, Fock cutoff 2) -> 64 probs + residual + LN.
//
// Each sample's 64-complex state is SPLIT across 2 threads on wire 0
// (bit 5 of the state index): thread h in {0,1} holds the 32 amplitudes
// with n_0 = h. Cross-thread gates (BS on wires (0,1), Disp on wire 0)
// use shfl.xor(1) butterflies. Everything else is thread-local with
// compile-time register indices.
//
// All var-derived gate coefficients are sample-independent: computed
// once per block into shared memory. Diagonal gate groups are merged:
//   D_A = Sq(v16..21) o Rot(v10..15)   (64-entry complex diag)
//   D_B = Rot(v32..37)
//   Kerr(v44..49): layer 2's is pure phase before |.|^2 -> dropped;
//   layer 1's is commuted through layer 2's first BS chain
//   (phi_i -> phi_i + a_i - a_{i+1}) and folded into layer 2's D_A.
// =====================================================================

#define FULLMASK 0xFFFFFFFFu

__device__ __forceinline__ float fast_sech(float r) {
    float e = __expf(r);
    return __fdividef(2.0f, e + __fdividef(1.0f, e));
}

// ---- local (within-thread) gates on the 32-complex half-state ----

template<int LO>
__device__ __forceinline__ void localBS(float* sr, float* si, float4 q) {
    const float c = q.x, esr = q.y, esi = q.z, c2 = q.w;
    const int HI = LO << 1;
#pragma unroll
    for (int p = 0; p < 8; ++p) {
        const int j00 = ((p & ~(LO - 1)) << 2) | (p & (LO - 1));
        const int j01 = j00 | LO, j10 = j00 | HI, j11 = j00 | HI | LO;
        float a01 = sr[j01], b01 = si[j01];
        float a10 = sr[j10], b10 = si[j10];
        sr[j01] = c * a01 + esr * a10 - esi * b10;
        si[j01] = c * b01 + esr * b10 + esi * a10;
        sr[j10] = c * a10 - esr * a01 - esi * b01;
        si[j10] = c * b10 - esr * b01 + esi * a01;
        sr[j11] *= c2; si[j11] *= c2;
    }
}

template<int M>
__device__ __forceinline__ void localDisp(float* sr, float* si, float4 m) {
#pragma unroll
    for (int p = 0; p < 16; ++p) {
        const int j0 = ((p & ~(M - 1)) << 1) | (p & (M - 1));
        const int j1 = j0 | M;
        float a0 = sr[j0], b0 = si[j0], a1 = sr[j1], b1 = si[j1];
        sr[j0] = m.x * a0 + m.y * a1;
        si[j0] = m.x * b0 + m.y * b1;
        sr[j1] = m.z * a0 + m.w * a1;
        si[j1] = m.z * b0 + m.w * b1;
    }
}

__device__ __forceinline__ void applyDiag(float* sr, float* si, const float2* __restrict__ D) {
#pragma unroll
    for (int j = 0; j < 32; ++j) {
        float2 d = D[j];
        float a = sr[j], b = si[j];
        sr[j] = a * d.x - b * d.y;
        si[j] = a * d.y + b * d.x;
    }
}

// ---- cross-thread gates ----

// BS on wires (0,1): global masks HI=32 (held as h), LO=16.
// h=0 thread owns j01 (local p|16); h=1 thread owns j10 (local p), j11 (local p|16).
__device__ __forceinline__ void crossBS(float* sr, float* si, float4 q, int h) {
    const float c = q.x, esi = q.z, c2 = q.w;
    const float e1 = h ? -q.y : q.y;
#pragma unroll
    for (int p = 0; p < 16; ++p) {
        float ar = h ? sr[p] : sr[p | 16];
        float ai = h ? si[p] : si[p | 16];
        float pr = __shfl_xor_sync(FULLMASK, ar, 1);
        float pi = __shfl_xor_sync(FULLMASK, ai, 1);
        float nr = c * ar + e1 * pr - esi * pi;
        float ni = c * ai + e1 * pi + esi * pr;
        if (h) {
            sr[p] = nr; si[p] = ni;
            sr[p | 16] *= c2; si[p | 16] *= c2;
        } else {
            sr[p | 16] = nr; si[p | 16] = ni;
        }
    }
}

// Disp on wire 0: mixes local j (h=0) with local j (h=1) for all 32 j.
__device__ __forceinline__ void crossDisp(float* sr, float* si, float4 m, int h) {
    const float a = h ? m.w : m.x;
    const float b = h ? m.z : m.y;
#pragma unroll
    for (int j = 0; j < 32; ++j) {
        float pr = __shfl_xor_sync(FULLMASK, sr[j], 1);
        float pi = __shfl_xor_sync(FULLMASK, si[j], 1);
        sr[j] = a * sr[j] + b * pr;
        si[j] = a * si[j] + b * pi;
    }
}

// ---- encoding: product-state expansion on the local half-state ----

template<int W>   // wires 1..5, local mask 1<<(5-W)
__device__ __forceinline__ void expandL(float* sr, float* si, float f0, float f1r, float f1i) {
    const int M = 1 << (5 - W);
#pragma unroll
    for (int t = 0; t < (1 << (W - 1)); ++t) {
        const int j = t << (6 - W);
        float a = sr[j], b = si[j];
        sr[j | M] = a * f1r - b * f1i;
        si[j | M] = a * f1i + b * f1r;
        sr[j] = a * f0;
        si[j] = b * f0;
    }
}

__device__ __forceinline__ void wire_factors(const float* __restrict__ xp, int w,
                                             float& f0, float& f1r, float& f1i) {
    float r1   = xp[2 * w];
    float dr   = xp[28 + 2 * w];
    float dphi = xp[29 + 2 * w];
    float kerr = xp[40 + w];
    float r2   = xp[46 + 2 * w];
    float rot2 = xp[58 + w];

    float sech1 = fast_sech(r1);
    float d01   = sqrtf(sech1);
    float pref  = __expf(-0.5f * dr * dr);
    float sech2 = fast_sech(r2);
    float d02   = sqrtf(sech2);
    float d12   = sech2 * d02;

    float base = d01 * pref;
    f0 = base * d02;
    float A = base * d12 * dr;
    float sA, cA;
    __sincosf(dphi + kerr + rot2, &sA, &cA);
    f1r = A * cA;
    f1i = A * sA;
}

// one variational layer on the half-state
__device__ __forceinline__ void apply_layer(float* sr, float* si,
                                            const float2* __restrict__ DA,
                                            const float2* __restrict__ DB,
                                            const float4* __restrict__ BS1,
                                            const float4* __restrict__ BS2,
                                            const float4* __restrict__ DSP,
                                            int h) {
    crossBS(sr, si, BS1[0], h);
    localBS<8>(sr, si, BS1[1]);
    localBS<4>(sr, si, BS1[2]);
    localBS<2>(sr, si, BS1[3]);
    localBS<1>(sr, si, BS1[4]);
    applyDiag(sr, si, DA + h * 32);
    crossBS(sr, si, BS2[0], h);
    localBS<8>(sr, si, BS2[1]);
    localBS<4>(sr, si, BS2[2]);
    localBS<2>(sr, si, BS2[3]);
    localBS<1>(sr, si, BS2[4]);
    applyDiag(sr, si, DB + h * 32);
    crossDisp(sr, si, DSP[0], h);
    localDisp<16>(sr, si, DSP[1]);
    localDisp<8 >(sr, si, DSP[2]);
    localDisp<4 >(sr, si, DSP[3]);
    localDisp<2 >(sr, si, DSP[4]);
    localDisp<1 >(sr, si, DSP[5]);
}

#define THREADS 256

extern "C" __global__ void __launch_bounds__(THREADS, 2)
ffblock_kernel(const float* __restrict__ x, const float* __restrict__ var,
               const float* __restrict__ gamma, const float* __restrict__ beta,
               float* __restrict__ out, int nsamp)
{
    __shared__ float2 sDA[2][64];
    __shared__ float2 sDB[2][64];
    __shared__ float4 sBS1[2][5];
    __shared__ float4 sBS2[2][5];
    __shared__ float4 sDSP[2][6];

    const int tid = threadIdx.x;

    // ---- per-block coefficient setup (var is shared by all samples) ----
    if (tid < 64) {
        const int j = tid;
        for (int l = 0; l < 2; ++l) {
            const float* v = var + 50 * l;
            float mag = 1.0f, phA = 0.0f, phB = 0.0f;
            for (int w = 0; w < 6; ++w) {
                int n = (j >> (5 - w)) & 1;
                float sh = fast_sech(v[16 + w]);
                float d0 = sqrtf(sh);
                mag *= n ? sh * d0 : d0;
                if (n) {
                    phA += v[10 + w] + (l ? var[44 + w] : 0.0f);  // fold layer-0 Kerr into layer-1 D_A
                    phB += v[32 + w];
                }
            }
            float s_, c_;
            __sincosf(phA, &s_, &c_);
            sDA[l][j] = make_float2(mag * c_, mag * s_);
            __sincosf(phB, &s_, &c_);
            sDB[l][j] = make_float2(c_, s_);
        }
    } else if (tid < 84) {
        int k = tid - 64;
        int isB2 = (k >= 10);
        if (isB2) k -= 10;
        int l = k / 5, i = k % 5;
        const float* v = var + 50 * l;
        float th, ph;
        if (isB2) { th = v[22 + 2 * i]; ph = v[23 + 2 * i]; }
        else {
            th = v[2 * i]; ph = v[2 * i + 1];
            if (l == 1) ph += var[44 + i] - var[44 + i + 1];  // Kerr phases commuted through BS
        }
        float st, ct, sp, cp;
        __sincosf(th, &st, &ct);
        __sincosf(ph, &sp, &cp);
        float4 q = make_float4(ct, st * cp, st * sp, 1.0f - 2.0f * st * st);
        if (isB2) sBS2[l][i] = q; else sBS1[l][i] = q;
    } else if (tid < 96) {
        int k = tid - 84;
        int l = k / 6, w = k % 6;
        const float* v = var + 50 * l;
        float r = v[38 + w];
        float pf = __expf(-0.5f * r * r);
        sDSP[l][w] = make_float4(pf, -pf * r, pf * r, pf * (1.0f - r * r));
    }
    __syncthreads();

    // ---- per-sample work: 2 threads per sample ----
    int gid = blockIdx.x * THREADS + tid;
    int sample = gid >> 1;
    if (sample >= nsamp) sample = nsamp - 1;   // pair-safe clamp (duplicate work)
    const int h = gid & 1;
    const float* xp = x + (size_t)sample * 64;

    float sr[32], si[32];
    {
        float f0, f1r, f1i;
        wire_factors(xp, 0, f0, f1r, f1i);
        sr[0] = h ? f1r : f0;
        si[0] = h ? f1i : 0.0f;
        wire_factors(xp, 1, f0, f1r, f1i); expandL<1>(sr, si, f0, f1r, f1i);
        wire_factors(xp, 2, f0, f1r, f1i); expandL<2>(sr, si, f0, f1r, f1i);
        wire_factors(xp, 3, f0, f1r, f1i); expandL<3>(sr, si, f0, f1r, f1i);
        wire_factors(xp, 4, f0, f1r, f1i); expandL<4>(sr, si, f0, f1r, f1i);
        wire_factors(xp, 5, f0, f1r, f1i); expandL<5>(sr, si, f0, f1r, f1i);
    }

    apply_layer(sr, si, sDA[0], sDB[0], sBS1[0], sBS2[0], sDSP[0], h);
    apply_layer(sr, si, sDA[1], sDB[1], sBS1[1], sBS2[1], sDSP[1], h);
    // (layer-2 Kerr rotations are pure phase before |.|^2 -> omitted)

    // ---- probs + residual + LayerNorm ----
    float sum = 0.0f, sumsq = 0.0f;
    const float* xr = xp + h * 32;
#pragma unroll
    for (int j = 0; j < 32; ++j) {
        float p = sr[j] * sr[j] + si[j] * si[j];
        float y = p + xr[j];
        sr[j] = y;
        sum += y;
        sumsq += y * y;
    }
    sum   += __shfl_xor_sync(FULLMASK, sum, 1);
    sumsq += __shfl_xor_sync(FULLMASK, sumsq, 1);
    float mean = sum * (1.0f / 64.0f);
    float varr = sumsq * (1.0f / 64.0f) - mean * mean;
    float inv = rsqrtf(varr + 1e-5f);

    float* op = out + (size_t)sample * 64 + h * 32;
    const float* gp = gamma + h * 32;
    const float* bp = beta + h * 32;
#pragma unroll
    for (int j = 0; j < 32; ++j) {
        op[j] = (sr[j] - mean) * inv * gp[j] + bp[j];
    }
}

extern "C" void kernel_launch(void* const* d_in, const int* in_sizes, int n_in,
                              void* d_out, int out_size) {
    const float* x     = (const float*)d_in[0];
    const float* var   = (const float*)d_in[1];
    const float* gamma = (const float*)d_in[2];
    const float* beta  = (const float*)d_in[3];
    float* out = (float*)d_out;

    int nsamp = in_sizes[0] / 64;
    int blocks = (2 * nsamp + THREADS - 1) / THREADS;
    ffblock_kernel<<<blocks, THREADS>>>(x, var, gamma, beta, out, nsamp);
}